// round 1
// baseline (speedup 1.0000x reference)
#include <cuda_runtime.h>
#include <stdint.h>

// SpikeFP32Floor: input is 2048*1024 fp32 values, each unpacked into 32
// floats (0.0/1.0), MSB-first. Output = same unpacking of floor(value),
// computed with the reference's exact bit semantics:
//   e < 127   -> sign ? bits(-1.0f) : 0
//   e >= 150  -> bits unchanged (incl. inf/nan)
//   otherwise -> clear low (150-e) mantissa bits; if negative and any
//                fractional bit was set, fp32 subtract 1.0 (exact here).
//
// One warp per value: lane L loads bit (31-L) as a float, ballot+brev packs
// the uint32, every lane computes the (warp-uniform) result word, lane L
// writes bit (31-L) back as 0.0/1.0. Fully coalesced 128B load + 128B store
// per warp; streaming cache hints since there is zero reuse.

__global__ void __launch_bounds__(256)
spike_floor_kernel(const float* __restrict__ x, float* __restrict__ out,
                   unsigned int n_vals)
{
    unsigned int tid  = blockIdx.x * blockDim.x + threadIdx.x;
    unsigned int wval = tid >> 5;          // which original fp32 value
    unsigned int lane = tid & 31u;
    if (wval >= n_vals) return;

    size_t idx = (size_t)wval * 32u + lane;

    // Load this lane's bit (exactly 0.0f or 1.0f).
    float fin = __ldcs(x + idx);
    unsigned int bit = (__float_as_uint(fin) != 0u) ? 1u : 0u;

    // ballot puts lane L's bit at position L; lane L holds bit (31-L) -> brev.
    unsigned int bal = __ballot_sync(0xFFFFFFFFu, bit);
    unsigned int u   = __brev(bal);

    // Warp-uniform floor-in-bits computation (no intra-warp divergence).
    unsigned int s = u & 0x80000000u;
    unsigned int e = (u >> 23) & 0xFFu;

    unsigned int r;
    if (e >= 150u) {
        r = u;                                   // already integer / inf / nan
    } else if (e < 127u) {
        r = s ? 0xBF800000u : 0u;                // -1.0f or +0.0f
    } else {
        unsigned int mask = (1u << (150u - e)) - 1u;  // fractional bits
        unsigned int t = u & ~mask;                    // truncate toward zero
        if (s && (u & mask)) {
            // negative with fractional part: exact fp32 subtract (|t|+1 <= 2^23)
            r = __float_as_uint(__uint_as_float(t) - 1.0f);
        } else {
            r = t;
        }
    }

    // Emit this lane's output bit as 0.0f / 1.0f.
    float fout = ((r >> (31u - lane)) & 1u) ? 1.0f : 0.0f;
    __stcs(out + idx, fout);
}

extern "C" void kernel_launch(void* const* d_in, const int* in_sizes, int n_in,
                              void* d_out, int out_size)
{
    const float* x = (const float*)d_in[0];
    float* out = (float*)d_out;

    unsigned int n_elems = (unsigned int)in_sizes[0];     // 2048*1024*32
    unsigned int n_vals  = n_elems >> 5;                  // one warp per value

    const int threads = 256;
    unsigned int blocks = (n_elems + threads - 1) / threads;

    spike_floor_kernel<<<blocks, threads>>>(x, out, n_vals);
}

// round 2
// speedup vs baseline: 2.4754x; 2.4754x over previous
#include <cuda_runtime.h>
#include <stdint.h>

// SpikeFP32Floor, round 2: float4 path.
//
// Input: 2048*1024 fp32 values, each unpacked MSB-first into 32 floats
// (0.0/1.0). Output: same unpacking of floor(value) with the reference's
// exact bit semantics.
//
// Warp layout: lane L loads a float4 (16B). A warp covers 512B = 4 values.
//   group g = L/8  -> which of the 4 values
//   slot  s = L%8  -> bit offsets 4s..4s+3 of that value (MSB-first)
// Pack: nibble from the 4 floats (1.0f == 0x3F800000, bit 29 set), shifted
// to position 28-4s, OR-reduced across the 8-lane group via 3x shfl_xor.
// Floor computed branchlessly (values differ across groups in one warp).
// Unpack: 4 bits -> float4, single STG.128.
//
// Each thread processes TWO float4s (front-batched loads, MLP=2/lane).
// Streaming cache hints: zero reuse.

__device__ __forceinline__ unsigned quad_nib(float4 v) {
    // 1.0f = 0x3F800000 (bit 29 set), 0.0f = 0. Route bit 29 to nibble slots.
    unsigned n;
    n  = (__float_as_uint(v.x) >> 26) & 8u;   // offset 4s   -> nib bit 3 (MSB)
    n |= (__float_as_uint(v.y) >> 27) & 4u;   // offset 4s+1 -> nib bit 2
    n |= (__float_as_uint(v.z) >> 28) & 2u;   // offset 4s+2 -> nib bit 1
    n |= (__float_as_uint(v.w) >> 29) & 1u;   // offset 4s+3 -> nib bit 0
    return n;
}

__device__ __forceinline__ unsigned floor_bits(unsigned u) {
    // Branchless bit-level floor, matching the reference:
    //   e >= 150 -> u unchanged (shc=0 -> mask=0 -> t=u, hasfrac=0)
    //   127 <= e < 150 -> clear low (150-e) mantissa bits; if negative and
    //                     fractional bits were set, exact fp32 t - 1.0f
    //   e < 127 -> sign ? bits(-1.0f) : 0   (final override)
    unsigned sgn = u & 0x80000000u;
    unsigned e   = (u >> 23) & 0xFFu;
    int d = 150 - (int)e;
    unsigned shc  = (unsigned)max(0, min(d, 23));
    unsigned mask = (1u << shc) - 1u;
    unsigned t    = u & ~mask;
    bool hasfrac  = (u & mask) != 0u;
    // Exact: |t| <= 2^23 scale in this branch; harmless (discarded) otherwise.
    unsigned tm1  = __float_as_uint(__uint_as_float(t) - 1.0f);
    unsigned r    = (sgn && hasfrac) ? tm1 : t;
    if (e < 127u) r = sgn ? 0xBF800000u : 0u;
    return r;
}

__device__ __forceinline__ float4 unpack_nib(unsigned r, unsigned sh) {
    unsigned no = r >> sh;
    float4 o;
    o.x = (no & 8u) ? 1.0f : 0.0f;
    o.y = (no & 4u) ? 1.0f : 0.0f;
    o.z = (no & 2u) ? 1.0f : 0.0f;
    o.w = (no & 1u) ? 1.0f : 0.0f;
    return o;
}

__global__ void __launch_bounds__(256)
spike_floor_v4(const float4* __restrict__ x, float4* __restrict__ out,
               unsigned int nquads)
{
    unsigned tid  = blockIdx.x * blockDim.x + threadIdx.x;
    unsigned lane = threadIdx.x & 31u;
    unsigned warp = tid >> 5;

    size_t base = (size_t)warp * 64u;          // 64 quads per warp (2/thread)
    if (base + 64u > (size_t)nquads) return;   // warp-uniform guard

    size_t q0 = base + lane;
    size_t q1 = q0 + 32u;

    // Front-batched loads (MLP=2 per lane).
    float4 a = __ldcs(&x[q0]);
    float4 b = __ldcs(&x[q1]);

    unsigned sh = 28u - 4u * (lane & 7u);

    unsigned wa = quad_nib(a) << sh;
    unsigned wb = quad_nib(b) << sh;

    // OR-reduce within each 8-lane group (xor 1,2,4 stays inside the group).
    wa |= __shfl_xor_sync(0xFFFFFFFFu, wa, 1);
    wb |= __shfl_xor_sync(0xFFFFFFFFu, wb, 1);
    wa |= __shfl_xor_sync(0xFFFFFFFFu, wa, 2);
    wb |= __shfl_xor_sync(0xFFFFFFFFu, wb, 2);
    wa |= __shfl_xor_sync(0xFFFFFFFFu, wa, 4);
    wb |= __shfl_xor_sync(0xFFFFFFFFu, wb, 4);

    unsigned ra = floor_bits(wa);
    unsigned rb = floor_bits(wb);

    float4 oa = unpack_nib(ra, sh);
    float4 ob = unpack_nib(rb, sh);

    __stcs(&out[q0], oa);
    __stcs(&out[q1], ob);
}

extern "C" void kernel_launch(void* const* d_in, const int* in_sizes, int n_in,
                              void* d_out, int out_size)
{
    const float4* x   = (const float4*)d_in[0];
    float4*       out = (float4*)d_out;

    unsigned n_elems = (unsigned)in_sizes[0];   // 2048*1024*32 floats
    unsigned nquads  = n_elems >> 2;            // float4 count
    unsigned threads_total = nquads >> 1;       // 2 quads per thread

    const int threads = 256;
    unsigned blocks = (threads_total + threads - 1) / threads;

    spike_floor_v4<<<blocks, threads>>>(x, out, nquads);
}